// round 14
// baseline (speedup 1.0000x reference)
#include <cuda_runtime.h>
#include <cuda_bf16.h>
#include <cstdint>

// Problem constants (fixed by the reference: N=4, T=1024, H=16, D_HEAD=64)
#define T_LEN 1024
#define HEADS 16
#define DH 64
#define NB_MAX 4
#define DM 1024

// ---------------------------------------------------------------------------
// Scratch (device globals — no allocation allowed in kernel_launch)
// ---------------------------------------------------------------------------
__device__ __align__(16) float g_R[(size_t)NB_MAX * HEADS * T_LEN * T_LEN]; // [bh][t][c], c=s-t+1023
__device__ __align__(16) __nv_bfloat16 g_xh[NB_MAX * T_LEN * DM];
__device__ __align__(16) __nv_bfloat16 g_xl[NB_MAX * T_LEN * DM];
__device__ __align__(16) __nv_bfloat16 g_wth[3 * DM * DM];  // W^T [mat][n][k]
__device__ __align__(16) __nv_bfloat16 g_wtl[3 * DM * DM];
__device__ __align__(16) __nv_bfloat16 g_qh[NB_MAX * HEADS * T_LEN * DH];
__device__ __align__(16) __nv_bfloat16 g_ql[NB_MAX * HEADS * T_LEN * DH];
__device__ __align__(16) __nv_bfloat16 g_kh[NB_MAX * HEADS * T_LEN * DH];
__device__ __align__(16) __nv_bfloat16 g_kl[NB_MAX * HEADS * T_LEN * DH];
__device__ __align__(16) __nv_bfloat16 g_vh[NB_MAX * HEADS * T_LEN * DH];
__device__ __align__(16) __nv_bfloat16 g_vl[NB_MAX * HEADS * T_LEN * DH];
__device__ __align__(16) __nv_bfloat16 g_erh[T_LEN * DH];
__device__ __align__(16) __nv_bfloat16 g_erl[T_LEN * DH];

// mma.sync m16n8k16 row.col f32.bf16.bf16.f32 (base PTX — works on sm_100)
#define MMA16816(d, a0, a1, a2, a3, b0, b1)                                   \
    asm volatile(                                                             \
        "mma.sync.aligned.m16n8k16.row.col.f32.bf16.bf16.f32 "                \
        "{%0,%1,%2,%3}, {%4,%5,%6,%7}, {%8,%9}, {%0,%1,%2,%3};"               \
        : "+f"((d)[0]), "+f"((d)[1]), "+f"((d)[2]), "+f"((d)[3])              \
        : "r"(a0), "r"(a1), "r"(a2), "r"(a3), "r"(b0), "r"(b1))

#define LDMX4(r0, r1, r2, r3, a)                                              \
    asm volatile("ldmatrix.sync.aligned.m8n8.x4.shared.b16 {%0,%1,%2,%3}, [%4];" \
                 : "=r"(r0), "=r"(r1), "=r"(r2), "=r"(r3) : "r"(a))
#define LDMX2(r0, r1, a)                                                      \
    asm volatile("ldmatrix.sync.aligned.m8n8.x2.shared.b16 {%0,%1}, [%2];"    \
                 : "=r"(r0), "=r"(r1) : "r"(a))
#define LDMX2T(r0, r1, a)                                                     \
    asm volatile("ldmatrix.sync.aligned.m8n8.x2.trans.shared.b16 {%0,%1}, [%2];" \
                 : "=r"(r0), "=r"(r1) : "r"(a))
#define CP16(dst_u32, src)                                                    \
    asm volatile("cp.async.cg.shared.global [%0], [%1], 16;"                  \
                 :: "r"(dst_u32), "l"(src))
#define CP_COMMIT() asm volatile("cp.async.commit_group;" ::: "memory")
#define CP_WAIT(n)  asm volatile("cp.async.wait_group %0;" :: "n"(n) : "memory")

__device__ __forceinline__ uint32_t smem_u32(const void* p) {
    uint32_t a;
    asm("{ .reg .u64 t; cvta.to.shared.u64 t, %1; cvt.u32.u64 %0, t; }"
        : "=r"(a) : "l"(p));
    return a;
}
__device__ __forceinline__ uint32_t pack_bf16(__nv_bfloat16 a, __nv_bfloat16 b) {
    __nv_bfloat162 t = __halves2bfloat162(a, b);
    return *(uint32_t*)&t;
}
__device__ __forceinline__ uint32_t pack_f2bf(float a, float b) {
    __nv_bfloat162 t = __floats2bfloat162_rn(a, b);
    return *(uint32_t*)&t;
}

// ---------------------------------------------------------------------------
// prep kernels: fp32 -> bf16 hi/lo splits (x, Er), W transpose+split
// ---------------------------------------------------------------------------
__global__ __launch_bounds__(256) void prep_x(const float* __restrict__ x, int n4)
{
    int i = blockIdx.x * 256 + threadIdx.x;
    if (i >= n4) return;
    float4 v = ((const float4*)x)[i];
    __nv_bfloat16 h[4], l[4];
    float f[4] = {v.x, v.y, v.z, v.w};
    #pragma unroll
    for (int j = 0; j < 4; j++) {
        h[j] = __float2bfloat16(f[j]);
        l[j] = __float2bfloat16(f[j] - __bfloat162float(h[j]));
    }
    __nv_bfloat162* oh = (__nv_bfloat162*)g_xh;
    __nv_bfloat162* ol = (__nv_bfloat162*)g_xl;
    oh[2 * i]     = __halves2bfloat162(h[0], h[1]);
    oh[2 * i + 1] = __halves2bfloat162(h[2], h[3]);
    ol[2 * i]     = __halves2bfloat162(l[0], l[1]);
    ol[2 * i + 1] = __halves2bfloat162(l[2], l[3]);
}

__global__ __launch_bounds__(256) void prep_er(const float* __restrict__ er)
{
    int i = blockIdx.x * 256 + threadIdx.x;
    if (i >= T_LEN * DH / 4) return;
    float4 v = ((const float4*)er)[i];
    float f[4] = {v.x, v.y, v.z, v.w};
    __nv_bfloat16 h[4], l[4];
    #pragma unroll
    for (int j = 0; j < 4; j++) {
        h[j] = __float2bfloat16(f[j]);
        l[j] = __float2bfloat16(f[j] - __bfloat162float(h[j]));
    }
    __nv_bfloat162* oh = (__nv_bfloat162*)g_erh;
    __nv_bfloat162* ol = (__nv_bfloat162*)g_erl;
    oh[2 * i]     = __halves2bfloat162(h[0], h[1]);
    oh[2 * i + 1] = __halves2bfloat162(h[2], h[3]);
    ol[2 * i]     = __halves2bfloat162(l[0], l[1]);
    ol[2 * i + 1] = __halves2bfloat162(l[2], l[3]);
}

__global__ __launch_bounds__(256) void prep_w(const float* __restrict__ Wq,
                                              const float* __restrict__ Wk,
                                              const float* __restrict__ Wv)
{
    const float* W = (blockIdx.z == 0) ? Wq : (blockIdx.z == 1) ? Wk : Wv;
    __shared__ float t[32][33];
    int tx = threadIdx.x, ty = threadIdx.y;        // 32 x 8
    int n0 = blockIdx.x * 32, k0 = blockIdx.y * 32;
    #pragma unroll
    for (int i = 0; i < 4; i++)
        t[ty + 8 * i][tx] = W[(size_t)(k0 + ty + 8 * i) * DM + n0 + tx];
    __syncthreads();
    __nv_bfloat16* oh = g_wth + (size_t)blockIdx.z * DM * DM;
    __nv_bfloat16* ol = g_wtl + (size_t)blockIdx.z * DM * DM;
    #pragma unroll
    for (int i = 0; i < 4; i++) {
        int n = n0 + ty + 8 * i;
        float v = t[tx][ty + 8 * i];
        __nv_bfloat16 h = __float2bfloat16(v);
        oh[(size_t)n * DM + k0 + tx] = h;
        ol[(size_t)n * DM + k0 + tx] = __float2bfloat16(v - __bfloat162float(h));
    }
}

// ---------------------------------------------------------------------------
// proj_mma: persistent grid, 128x128 tiles, 3-pass bf16 hi/lo HMMA,
// cp.async 2-stage pipeline, ldmatrix. NEW: A-fragment software pipeline
// across mf (double-buffered) to overlap LDSM latency with MMA bursts.
// ---------------------------------------------------------------------------
#define KC 32
#define NCHUNK (DM / KC)            // 32
#define SPAD 40                     // smem row stride in bf16 (80 B)
#define ARR_B (128 * SPAD * 2)      // 10240 bytes per array
#define STAGE_B (4 * ARR_B)         // 40960
#define PROJ_SMEM (2 * STAGE_B)     // 81920
#define PROJ_GRID 592               // 2 CTAs x 296 slots (148 SMs x 2)

__global__ __launch_bounds__(256, 2) void proj_mma(const float* __restrict__ bq,
                                                   const float* __restrict__ bk,
                                                   const float* __restrict__ bv,
                                                   int nTiles, int mTiles)
{
    extern __shared__ char sm[];
    uint32_t smb = smem_u32(sm);

    int tid = threadIdx.x;
    int wid = tid >> 5, lane = tid & 31;
    int g = lane >> 2, tig = lane & 3;
    int l15 = lane & 15;
    int wm = wid >> 2, wn = wid & 3;             // 2 x 4 warp grid

    int r0 = tid >> 2, c0 = (tid & 3) * 8;       // cp.async row, bf16-col
    uint32_t dOff0 = (uint32_t)(r0 * 80 + c0 * 2);
    uint32_t dOff1 = dOff0 + 64 * 80;

    uint32_t aOff = (uint32_t)(((wm * 64) + (lane & 7) + ((lane >> 3) & 1) * 8) * 80
                               + (lane >> 4) * 16);
    uint32_t bOff = (uint32_t)(((wn * 32) + (l15 & 7)) * 80 + (l15 >> 3) * 16);

    int tilesPerMat = mTiles * 8;                 // 8 n-tiles per mat
    int total = 3 * tilesPerMat;

    #pragma unroll 1
    for (int tile = blockIdx.x; tile < total; tile += gridDim.x) {
        int mat = tile / tilesPerMat;
        int rem = tile - mat * tilesPerMat;
        int n0 = (rem & 7) << 7;
        int m0 = (rem >> 3) << 7;

        const float* bias = (mat == 0) ? bq : (mat == 1) ? bk : bv;
        __nv_bfloat16* outh = (mat == 0) ? g_qh : (mat == 1) ? g_kh : g_vh;
        __nv_bfloat16* outl = (mat == 0) ? g_ql : (mat == 1) ? g_kl : g_vl;
        const __nv_bfloat16* srcs[4] = {
            g_xh + (size_t)m0 * DM,
            g_xl + (size_t)m0 * DM,
            g_wth + (size_t)mat * DM * DM + (size_t)n0 * DM,
            g_wtl + (size_t)mat * DM * DM + (size_t)n0 * DM };

        float acc[4][4][4];
        #pragma unroll
        for (int i = 0; i < 4; i++)
            #pragma unroll
            for (int j = 0; j < 4; j++)
                #pragma unroll
                for (int r = 0; r < 4; r++) acc[i][j][r] = 0.f;

        auto issue = [&](int c) {
            uint32_t sb = smb + (uint32_t)(c & 1) * STAGE_B;
            int k0 = c * KC;
            #pragma unroll
            for (int a = 0; a < 4; a++) {
                const __nv_bfloat16* s = srcs[a] + k0;
                uint32_t d = sb + (uint32_t)a * ARR_B;
                CP16(d + dOff0, s + (size_t)r0 * DM + c0);
                CP16(d + dOff1, s + (size_t)(r0 + 64) * DM + c0);
            }
            CP_COMMIT();
        };

        issue(0);

        #pragma unroll 1
        for (int c = 0; c < NCHUNK; c++) {
            if (c + 1 < NCHUNK) { issue(c + 1); CP_WAIT(1); }
            else                { CP_WAIT(0); }
            __syncthreads();

            uint32_t sb = smb + (uint32_t)(c & 1) * STAGE_B;
            uint32_t aH = sb + aOff;
            uint32_t aL = sb + ARR_B + aOff;
            uint32_t bH = sb + 2 * ARR_B + bOff;
            uint32_t bL = sb + 3 * ARR_B + bOff;

            #pragma unroll
            for (int kk = 0; kk < 2; kk++) {
                uint32_t kb = (uint32_t)kk * 32;   // 16 cols * 2B
                uint32_t vbh[4][2], vbl[4][2];
                #pragma unroll
                for (int nf = 0; nf < 4; nf++) {
                    LDMX2(vbh[nf][0], vbh[nf][1], bH + (uint32_t)nf * 640 + kb);
                    LDMX2(vbl[nf][0], vbl[nf][1], bL + (uint32_t)nf * 640 + kb);
                }
                // A-fragment software pipeline: double buffer across mf.
                uint32_t af[2][8];
                LDMX4(af[0][0], af[0][1], af[0][2], af[0][3], aH + kb);
                LDMX4(af[0][4], af[0][5], af[0][6], af[0][7], aL + kb);
                #pragma unroll
                for (int mf = 0; mf < 4; mf++) {
                    int cur = mf & 1, nxt = cur ^ 1;
                    if (mf < 3) {
                        LDMX4(af[nxt][0], af[nxt][1], af[nxt][2], af[nxt][3],
                              aH + (uint32_t)(mf + 1) * 1280 + kb);
                        LDMX4(af[nxt][4], af[nxt][5], af[nxt][6], af[nxt][7],
                              aL + (uint32_t)(mf + 1) * 1280 + kb);
                    }
                    #pragma unroll
                    for (int nf = 0; nf < 4; nf++)
                        MMA16816(acc[mf][nf], af[cur][0], af[cur][1], af[cur][2],
                                 af[cur][3], vbh[nf][0], vbh[nf][1]);
                    #pragma unroll
                    for (int nf = 0; nf < 4; nf++)
                        MMA16816(acc[mf][nf], af[cur][0], af[cur][1], af[cur][2],
                                 af[cur][3], vbl[nf][0], vbl[nf][1]);
                    #pragma unroll
                    for (int nf = 0; nf < 4; nf++)
                        MMA16816(acc[mf][nf], af[cur][4], af[cur][5], af[cur][6],
                                 af[cur][7], vbh[nf][0], vbh[nf][1]);
                }
            }
            __syncthreads();
        }

        // Epilogue: bias + split to bf16 hi/lo + scatter to [b,h,t,d]
        #pragma unroll
        for (int mf = 0; mf < 4; mf++) {
            #pragma unroll
            for (int nf = 0; nf < 4; nf++) {
                int n = n0 + wn * 32 + nf * 8 + tig * 2;
                int h = n >> 6, d = n & 63;
                float b0 = bias[n], b1 = bias[n + 1];
                #pragma unroll
                for (int half = 0; half < 2; half++) {
                    int m = m0 + wm * 64 + mf * 16 + g + half * 8;
                    int b = m >> 10, t = m & 1023;
                    size_t idx = (((size_t)b * HEADS + h) * T_LEN + t) * DH + d;
                    float v0 = acc[mf][nf][half * 2] + b0;
                    float v1 = acc[mf][nf][half * 2 + 1] + b1;
                    __nv_bfloat16 h0 = __float2bfloat16(v0);
                    __nv_bfloat16 h1 = __float2bfloat16(v1);
                    *(uint32_t*)&outh[idx] = pack_bf16(h0, h1);
                    *(uint32_t*)&outl[idx] = pack_f2bf(v0 - __bfloat162float(h0),
                                                       v1 - __bfloat162float(h1));
                }
            }
        }
        __syncthreads();   // epilogue done before next tile reuses smem
    }
}

// ---------------------------------------------------------------------------
// rel_mma: banded R[bh][t][c] = q[bh][t].Er[c] on HMMA (3-pass hi/lo).
// ---------------------------------------------------------------------------
#define EPAD 72
#define EROW (EPAD * 2)   // 144 bytes

__global__ __launch_bounds__(128) void rel_mma()
{
    __shared__ __nv_bfloat16 sEh[64][EPAD];
    __shared__ __nv_bfloat16 sEl[64][EPAD];

    int sb = blockIdx.x, tb = blockIdx.y, bh = blockIdx.z;
    if (tb + sb < 15) return;   // tile never read under causal mask

    int tid = threadIdx.x, w = tid >> 5, lane = tid & 31;
    int l15 = lane & 15;
    int t0 = tb * 64, s0 = sb * 64;

    const __nv_bfloat16* qh = g_qh + (size_t)bh * T_LEN * DH;
    const __nv_bfloat16* ql = g_ql + (size_t)bh * T_LEN * DH;

    for (int i = tid; i < 512; i += 128) {
        int r = i >> 3, c = (i & 7) * 8;
        *(uint4*)&sEh[r][c] = *(const uint4*)&g_erh[(s0 + r) * DH + c];
        *(uint4*)&sEl[r][c] = *(const uint4*)&g_erl[(s0 + r) * DH + c];
    }

    int rowA = t0 + w * 16 + (lane >> 2);
    int tig = lane & 3;
    uint32_t qfh[4][4], qfl[4][4];
    #pragma unroll
    for (int ks = 0; ks < 4; ks++) {
        int d0 = ks * 16 + tig * 2;
        qfh[ks][0] = *(const uint32_t*)&qh[(size_t)rowA * DH + d0];
        qfh[ks][1] = *(const uint32_t*)&qh[(size_t)(rowA + 8) * DH + d0];
        qfh[ks][2] = *(const uint32_t*)&qh[(size_t)rowA * DH + d0 + 8];
        qfh[ks][3] = *(const uint32_t*)&qh[(size_t)(rowA + 8) * DH + d0 + 8];
        qfl[ks][0] = *(const uint32_t*)&ql[(size_t)rowA * DH + d0];
        qfl[ks][1] = *(const uint32_t*)&ql[(size_t)(rowA + 8) * DH + d0];
        qfl[ks][2] = *(const uint32_t*)&ql[(size_t)rowA * DH + d0 + 8];
        qfl[ks][3] = *(const uint32_t*)&ql[(size_t)(rowA + 8) * DH + d0 + 8];
    }
    __syncthreads();

    float acc[8][4];
    #pragma unroll
    for (int f = 0; f < 8; f++)
        #pragma unroll
        for (int r = 0; r < 4; r++) acc[f][r] = 0.f;

    uint32_t eOff = (uint32_t)((l15 & 7) * EROW + (l15 >> 3) * 16);
    uint32_t eH = smem_u32(&sEh[0][0]) + eOff;
    uint32_t eL = smem_u32(&sEl[0][0]) + eOff;

    #pragma unroll
    for (int ks = 0; ks < 4; ks++) {
        uint32_t kb = (uint32_t)ks * 32;
        uint32_t ebh[8][2], ebl[8][2];
        #pragma unroll
        for (int nf = 0; nf < 8; nf++) {
            LDMX2(ebh[nf][0], ebh[nf][1], eH + (uint32_t)nf * 8 * EROW + kb);
            LDMX2(ebl[nf][0], ebl[nf][1], eL + (uint32_t)nf * 8 * EROW + kb);
        }
        #pragma unroll
        for (int nf = 0; nf < 8; nf++)
            MMA16816(acc[nf], qfh[ks][0], qfh[ks][1], qfh[ks][2], qfh[ks][3],
                     ebh[nf][0], ebh[nf][1]);
        #pragma unroll
        for (int nf = 0; nf < 8; nf++)
            MMA16816(acc[nf], qfh[ks][0], qfh[ks][1], qfh[ks][2], qfh[ks][3],
                     ebl[nf][0], ebl[nf][1]);
        #pragma unroll
        for (int nf = 0; nf < 8; nf++)
            MMA16816(acc[nf], qfl[ks][0], qfl[ks][1], qfl[ks][2], qfl[ks][3],
                     ebh[nf][0], ebh[nf][1]);
    }

    float* Rg = g_R + (size_t)bh * T_LEN * T_LEN;
    #pragma unroll
    for (int nf = 0; nf < 8; nf++) {
        int c = s0 + nf * 8 + tig * 2;
        *(float2*)&Rg[(size_t)rowA * T_LEN + c] = make_float2(acc[nf][0], acc[nf][1]);
        *(float2*)&Rg[(size_t)(rowA + 8) * T_LEN + c] = make_float2(acc[nf][2], acc[nf][3]);
    }
}

// ---------------------------------------------------------------------------
// attn_mma: FA2 flash attention on HMMA (3-pass hi/lo).
// 128-row t-tile, 256 threads. cp.async double-buffered K/V tiles.
// Heavy tiles launched FIRST (tb reversed) to shrink the tail wave.
// ---------------------------------------------------------------------------
#define ARR_AT (64 * EROW)          // 9216 B per array (64 rows x 144 B)
#define STAGE_AT (4 * ARR_AT)       // 36864
#define AT_SMEM (2 * STAGE_AT)      // 73728

__global__ __launch_bounds__(256, 1) void attn_mma(float* __restrict__ out)
{
    extern __shared__ char smA[];
    uint32_t smb = smem_u32(smA);

    int tid = threadIdx.x, w = tid >> 5, lane = tid & 31;
    int g = lane >> 2, tig = lane & 3;
    int l15 = lane & 15;
    int tb = (int)gridDim.x - 1 - (int)blockIdx.x;   // heavy tiles first
    int bh = blockIdx.y;
    int t0 = tb * 128;

    const __nv_bfloat16* qh = g_qh + (size_t)bh * T_LEN * DH;
    const __nv_bfloat16* ql = g_ql + (size_t)bh * T_LEN * DH;
    const __nv_bfloat16* kh = g_kh + (size_t)bh * T_LEN * DH;
    const __nv_bfloat16* kl = g_kl + (size_t)bh * T_LEN * DH;
    const __nv_bfloat16* vh = g_vh + (size_t)bh * T_LEN * DH;
    const __nv_bfloat16* vl = g_vl + (size_t)bh * T_LEN * DH;
    const float* Rg = g_R + (size_t)bh * T_LEN * T_LEN;

    int rowA = t0 + w * 16 + g;          // warp w covers rows [t0+16w, t0+16w+16)
    int row1 = rowA + 8;

    // Q fragments (held for the whole kernel)
    uint32_t qfh[4][4], qfl[4][4];
    #pragma unroll
    for (int ks = 0; ks < 4; ks++) {
        int d0 = ks * 16 + tig * 2;
        qfh[ks][0] = *(const uint32_t*)&qh[(size_t)rowA * DH + d0];
        qfh[ks][1] = *(const uint32_t*)&qh[(size_t)row1 * DH + d0];
        qfh[ks][2] = *(const uint32_t*)&qh[(size_t)rowA * DH + d0 + 8];
        qfh[ks][3] = *(const uint32_t*)&qh[(size_t)row1 * DH + d0 + 8];
        qfl[ks][0] = *(const uint32_t*)&ql[(size_t)rowA * DH + d0];
        qfl[ks][1] = *(const uint32_t*)&ql[(size_t)row1 * DH + d0];
        qfl[ks][2] = *(const uint32_t*)&ql[(size_t)rowA * DH + d0 + 8];
        qfl[ks][3] = *(const uint32_t*)&ql[(size_t)row1 * DH + d0 + 8];
    }

    float m0 = -1e30f, m1 = -1e30f, l0 = 0.f, l1 = 0.f;
    float o[8][4];
    #pragma unroll
    for (int f = 0; f < 8; f++)
        #pragma unroll
        for (int r = 0; r < 4; r++) o[f][r] = 0.f;

    const float* R0 = Rg + (size_t)rowA * T_LEN + (T_LEN - 1 - rowA);
    const float* R1 = Rg + (size_t)row1 * T_LEN + (T_LEN - 1 - row1);

    // cp.async mapping: 256 threads cover 512 x 16B per array (64 rows x 128B)
    int cr0 = tid >> 3;                     // rows 0..31 (and +32)
    int cc0 = (tid & 7) * 8;                // bf16 col
    uint32_t cOff0 = (uint32_t)(cr0 * EROW + cc0 * 2);
    uint32_t cOff1 = cOff0 + 32 * EROW;
    const __nv_bfloat16* kvsrc[4] = {kh, kl, vh, vl};

    auto issueKV = [&](int sbt) {
        uint32_t st = smb + (uint32_t)(sbt & 1) * STAGE_AT;
        int s0 = sbt * 64;
        #pragma unroll
        for (int a = 0; a < 4; a++) {
            const __nv_bfloat16* s = kvsrc[a] + (size_t)s0 * DH;
            uint32_t d = st + (uint32_t)a * ARR_AT;
            CP16(d + cOff0, s + (size_t)cr0 * DH + cc0);
            CP16(d + cOff1, s + (size_t)(cr0 + 32) * DH + cc0);
        }
        CP_COMMIT();
    };

    // ldmatrix per-lane offsets (relative to array base)
    uint32_t kOff = (uint32_t)((l15 & 7) * EROW + (l15 >> 3) * 16);
    uint32_t vOff = (uint32_t)(((l15 & 7) + (l15 >> 3) * 8) * EROW);

    int sbMax = 2 * tb + 1;
    issueKV(0);

    #pragma unroll 1
    for (int sb = 0; sb <= sbMax; sb++) {
        int s0 = sb * 64;
        if (sb + 1 <= sbMax) { issueKV(sb + 1); CP_WAIT(1); }
        else                 { CP_WAIT(0); }
        __syncthreads();

        uint32_t st = smb + (uint32_t)(sb & 1) * STAGE_AT;
        uint32_t kBH = st + kOff;
        uint32_t kBL = st + ARR_AT + kOff;
        uint32_t vBH = st + 2 * ARR_AT + vOff;
        uint32_t vBL = st + 3 * ARR_AT + vOff;

        // S = Q @ K^T (3-pass, pass-major)
        float s[8][4];
        #pragma unroll
        for (int f = 0; f < 8; f++)
            #pragma unroll
            for (int r = 0; r < 4; r++) s[f][r] = 0.f;

        #pragma unroll
        for (int ks = 0; ks < 4; ks++) {
            uint32_t kb = (uint32_t)ks * 32;
            uint32_t kbh[8][2], kbl[8][2];
            #pragma unroll
            for (int nf = 0; nf < 8; nf++) {
                LDMX2(kbh[nf][0], kbh[nf][1], kBH + (uint32_t)nf * 8 * EROW + kb);
                LDMX2(kbl[nf][0], kbl[nf][1], kBL + (uint32_t)nf * 8 * EROW + kb);
            }
            #pragma unroll
            for (int nf = 0; nf < 8; nf++)
                MMA16816(s[nf], qfh[ks][0], qfh[ks][1], qfh[ks][2], qfh[ks][3],
                         kbh[nf][0], kbh[nf][1]);
            #pragma unroll
            for (int nf = 0; nf < 8; nf++)
                MMA16816(s[nf], qfh[ks][0], qfh[ks][1], qfh[ks][2], qfh[ks][3],
                         kbl[nf][0], kbl[nf][1]);
            #pragma unroll
            for (int nf = 0; nf < 8; nf++)
                MMA16816(s[nf], qfl[ks][0], qfl[ks][1], qfl[ks][2], qfl[ks][3],
                         kbh[nf][0], kbh[nf][1]);
        }

        // rel add + scale + causal mask (clamped indices keep loads in-bounds)
        #pragma unroll
        for (int nf = 0; nf < 8; nf++) {
            int sc = s0 + nf * 8 + tig * 2;
            float r00 = R0[min(sc, rowA)];
            float r01 = R0[min(sc + 1, rowA)];
            float r10 = R1[min(sc, row1)];
            float r11 = R1[min(sc + 1, row1)];
            s[nf][0] = (sc     <= rowA) ? (s[nf][0] + r00) * 0.125f : -1e30f;
            s[nf][1] = (sc + 1 <= rowA) ? (s[nf][1] + r01) * 0.125f : -1e30f;
            s[nf][2] = (sc     <= row1) ? (s[nf][2] + r10) * 0.125f : -1e30f;
            s[nf][3] = (sc + 1 <= row1) ? (s[nf][3] + r11) * 0.125f : -1e30f;
        }

        // online softmax (rows rowA, row1); cols spread over quad (tig)
        float mx0 = -1e30f, mx1 = -1e30f;
        #pragma unroll
        for (int nf = 0; nf < 8; nf++) {
            mx0 = fmaxf(mx0, fmaxf(s[nf][0], s[nf][1]));
            mx1 = fmaxf(mx1, fmaxf(s[nf][2], s[nf][3]));
        }
        mx0 = fmaxf(mx0, __shfl_xor_sync(0xffffffffu, mx0, 1));
        mx0 = fmaxf(mx0, __shfl_xor_sync(0xffffffffu, mx0, 2));
        mx1 = fmaxf(mx1, __shfl_xor_sync(0xffffffffu, mx1, 1));
        mx1 = fmaxf(mx1, __shfl_xor_sync(0xffffffffu, mx1, 2));

        float mn0 = fmaxf(m0, mx0), a0 = __expf(m0 - mn0); m0 = mn0;
        float mn1 = fmaxf(m1, mx1), a1 = __expf(m1 - mn1); m1 = mn1;

        float rs0 = 0.f, rs1 = 0.f;
        #pragma unroll
        for (int nf = 0; nf < 8; nf++) {
            s[nf][0] = __expf(s[nf][0] - mn0);
            s[nf][1] = __expf(s[nf][1] - mn0);
            s[nf][2] = __expf(s[nf][2] - mn1);
            s[nf][3] = __expf(s[nf][3] - mn1);
            rs0 += s[nf][0] + s[nf][1];
            rs1 += s[nf][2] + s[nf][3];
        }
        rs0 += __shfl_xor_sync(0xffffffffu, rs0, 1);
        rs0 += __shfl_xor_sync(0xffffffffu, rs0, 2);
        rs1 += __shfl_xor_sync(0xffffffffu, rs1, 1);
        rs1 += __shfl_xor_sync(0xffffffffu, rs1, 2);
        l0 = l0 * a0 + rs0;
        l1 = l1 * a1 + rs1;
        #pragma unroll
        for (int f = 0; f < 8; f++) {
            o[f][0] *= a0; o[f][1] *= a0;
            o[f][2] *= a1; o[f][3] *= a1;
        }

        // P -> bf16 hi/lo A-fragments (register reuse: c0..c3 == a0..a3)
        uint32_t ph[8][2], pl[8][2];
        #pragma unroll
        for (int f = 0; f < 8; f++) {
            __nv_bfloat16 h00 = __float2bfloat16(s[f][0]);
            __nv_bfloat16 h01 = __float2bfloat16(s[f][1]);
            __nv_bfloat16 h10 = __float2bfloat16(s[f][2]);
            __nv_bfloat16 h11 = __float2bfloat16(s[f][3]);
            ph[f][0] = pack_bf16(h00, h01);
            ph[f][1] = pack_bf16(h10, h11);
            pl[f][0] = pack_f2bf(s[f][0] - __bfloat162float(h00),
                                 s[f][1] - __bfloat162float(h01));
            pl[f][1] = pack_f2bf(s[f][2] - __bfloat162float(h10),
                                 s[f][3] - __bfloat162float(h11));
        }

        // O += P @ V (3-pass, pass-major); V B-frags via ldmatrix.trans
        #pragma unroll
        for (int j = 0; j < 4; j++) {
            uint32_t aH0 = ph[2 * j][0], aH1 = ph[2 * j][1];
            uint32_t aH2 = ph[2 * j + 1][0], aH3 = ph[2 * j + 1][1];
            uint32_t aL0 = pl[2 * j][0], aL1 = pl[2 * j][1];
            uint32_t aL2 = pl[2 * j + 1][0], aL3 = pl[2 * j + 1][1];
            uint32_t jrow = (uint32_t)(j * 16) * EROW;
            uint32_t vbh[8][2], vbl[8][2];
            #pragma unroll
            for (int nf = 0; nf < 8; nf++) {
                LDMX2T(vbh[nf][0], vbh[nf][1], vBH + jrow + (uint32_t)nf * 16);
                LDMX2T(vbl[nf][0], vbl[nf][1], vBL + jrow + (uint32_t)nf * 16);
            }
            #pragma unroll
            for (int nf = 0; nf < 8; nf++)
                MMA16816(o[nf], aH0, aH1, aH2, aH3, vbh[nf][0], vbh[nf][1]);
            #pragma unroll
            for (int nf = 0; nf < 8; nf++)
                MMA16816(o[nf], aH0, aH1, aH2, aH3, vbl[nf][0], vbl[nf][1]);
            #pragma unroll
            for (int nf = 0; nf < 8; nf++)
                MMA16816(o[nf], aL0, aL1, aL2, aL3, vbh[nf][0], vbh[nf][1]);
        }
        __syncthreads();   // all reads of this stage done before issueKV reuses it
    }

    // epilogue: out[b][t][h*64+d]
    int b = bh >> 4, h = bh & 15;
    float i0 = 1.f / l0, i1 = 1.f / l1;
    #pragma unroll
    for (int nf = 0; nf < 8; nf++) {
        int d = nf * 8 + tig * 2;
        float* op0 = out + ((size_t)b * T_LEN + rowA) * DM + h * DH + d;
        float* op1 = out + ((size_t)b * T_LEN + row1) * DM + h * DH + d;
        *(float2*)op0 = make_float2(o[nf][0] * i0, o[nf][1] * i0);
        *(float2*)op1 = make_float2(o[nf][2] * i1, o[nf][3] * i1);
    }
}

// ---------------------------------------------------------------------------
extern "C" void kernel_launch(void* const* d_in, const int* in_sizes, int n_in,
                              void* d_out, int out_size)
{
    const float* x  = (const float*)d_in[0];
    const float* Wq = (const float*)d_in[1];
    const float* bq = (const float*)d_in[2];
    const float* Wk = (const float*)d_in[3];
    const float* bk = (const float*)d_in[4];
    const float* Wv = (const float*)d_in[5];
    const float* bv = (const float*)d_in[6];
    const float* Er = (const float*)d_in[7];
    float* out = (float*)d_out;

    int NB = in_sizes[0] / (T_LEN * DM);
    if (NB > NB_MAX) NB = NB_MAX;

    cudaFuncSetAttribute(proj_mma, cudaFuncAttributeMaxDynamicSharedMemorySize,
                         PROJ_SMEM);
    cudaFuncSetAttribute(attn_mma, cudaFuncAttributeMaxDynamicSharedMemorySize,
                         AT_SMEM);

    // 0) split x / Er, transpose+split W to bf16 hi/lo
    int n4 = NB * T_LEN * DM / 4;
    prep_x<<<(n4 + 255) / 256, 256>>>(x, n4);
    prep_er<<<(T_LEN * DH / 4 + 255) / 256, 256>>>(Er);
    prep_w<<<dim3(32, 32, 3), dim3(32, 8)>>>(Wq, Wk, Wv);

    // 1) q,k,v projections: persistent grid, A-fragment software pipeline
    int mTiles = NB * 8;
    int totalTiles = 3 * mTiles * 8;
    int pgrid = totalTiles < PROJ_GRID ? totalTiles : PROJ_GRID;
    proj_mma<<<pgrid, 256, PROJ_SMEM>>>(bq, bk, bv, 8, mTiles);

    // 2) relative scores R = q @ Er^T (banded) on HMMA
    dim3 rgrid(16, 16, NB * HEADS);
    rel_mma<<<rgrid, 128>>>();

    // 3) flash attention on HMMA (128-row t-tiles, heavy-first order)
    dim3 agrid(8, NB * HEADS);
    attn_mma<<<agrid, 256, AT_SMEM>>>(out);
}

// round 15
// speedup vs baseline: 1.1579x; 1.1579x over previous
#include <cuda_runtime.h>
#include <cuda_bf16.h>
#include <cstdint>

// Problem constants (fixed by the reference: N=4, T=1024, H=16, D_HEAD=64)
#define T_LEN 1024
#define HEADS 16
#define DH 64
#define NB_MAX 4
#define DM 1024

// ---------------------------------------------------------------------------
// Scratch (device globals — no allocation allowed in kernel_launch)
// ---------------------------------------------------------------------------
__device__ __align__(16) float g_R[(size_t)NB_MAX * HEADS * T_LEN * T_LEN]; // [bh][t][c], c=s-t+1023
__device__ __align__(16) float g_xt[NB_MAX * T_LEN * DM];   // x, tf32-truncated
__device__ __align__(16) float g_wt[3 * DM * DM];           // W^T [mat][n][k], tf32
__device__ __align__(16) __nv_bfloat16 g_qh[NB_MAX * HEADS * T_LEN * DH];
__device__ __align__(16) __nv_bfloat16 g_ql[NB_MAX * HEADS * T_LEN * DH];
__device__ __align__(16) __nv_bfloat16 g_kh[NB_MAX * HEADS * T_LEN * DH];
__device__ __align__(16) __nv_bfloat16 g_kl[NB_MAX * HEADS * T_LEN * DH];
__device__ __align__(16) __nv_bfloat16 g_vh[NB_MAX * HEADS * T_LEN * DH];
__device__ __align__(16) __nv_bfloat16 g_vl[NB_MAX * HEADS * T_LEN * DH];
__device__ __align__(16) __nv_bfloat16 g_erh[T_LEN * DH];
__device__ __align__(16) __nv_bfloat16 g_erl[T_LEN * DH];

// mma.sync m16n8k16 row.col f32.bf16.bf16.f32 (base PTX — works on sm_100)
#define MMA16816(d, a0, a1, a2, a3, b0, b1)                                   \
    asm volatile(                                                             \
        "mma.sync.aligned.m16n8k16.row.col.f32.bf16.bf16.f32 "                \
        "{%0,%1,%2,%3}, {%4,%5,%6,%7}, {%8,%9}, {%0,%1,%2,%3};"               \
        : "+f"((d)[0]), "+f"((d)[1]), "+f"((d)[2]), "+f"((d)[3])              \
        : "r"(a0), "r"(a1), "r"(a2), "r"(a3), "r"(b0), "r"(b1))

// mma.sync m16n8k8 tf32 (base PTX sm_80+): same reg signature (4 A, 2 B, 4 C)
#define MMATF32(d, a0, a1, a2, a3, b0, b1)                                    \
    asm volatile(                                                             \
        "mma.sync.aligned.m16n8k8.row.col.f32.tf32.tf32.f32 "                 \
        "{%0,%1,%2,%3}, {%4,%5,%6,%7}, {%8,%9}, {%0,%1,%2,%3};"               \
        : "+f"((d)[0]), "+f"((d)[1]), "+f"((d)[2]), "+f"((d)[3])              \
        : "r"(a0), "r"(a1), "r"(a2), "r"(a3), "r"(b0), "r"(b1))

#define LDMX4(r0, r1, r2, r3, a)                                              \
    asm volatile("ldmatrix.sync.aligned.m8n8.x4.shared.b16 {%0,%1,%2,%3}, [%4];" \
                 : "=r"(r0), "=r"(r1), "=r"(r2), "=r"(r3) : "r"(a))
#define LDMX2(r0, r1, a)                                                      \
    asm volatile("ldmatrix.sync.aligned.m8n8.x2.shared.b16 {%0,%1}, [%2];"    \
                 : "=r"(r0), "=r"(r1) : "r"(a))
#define LDMX2T(r0, r1, a)                                                     \
    asm volatile("ldmatrix.sync.aligned.m8n8.x2.trans.shared.b16 {%0,%1}, [%2];" \
                 : "=r"(r0), "=r"(r1) : "r"(a))
#define CP16(dst_u32, src)                                                    \
    asm volatile("cp.async.cg.shared.global [%0], [%1], 16;"                  \
                 :: "r"(dst_u32), "l"(src))
#define CP_COMMIT() asm volatile("cp.async.commit_group;" ::: "memory")
#define CP_WAIT(n)  asm volatile("cp.async.wait_group %0;" :: "n"(n) : "memory")

__device__ __forceinline__ uint32_t smem_u32(const void* p) {
    uint32_t a;
    asm("{ .reg .u64 t; cvta.to.shared.u64 t, %1; cvt.u32.u64 %0, t; }"
        : "=r"(a) : "l"(p));
    return a;
}
__device__ __forceinline__ float to_tf32(float x) {
    uint32_t b;
    asm("cvt.rna.tf32.f32 %0, %1;" : "=r"(b) : "f"(x));
    return __uint_as_float(b);
}
__device__ __forceinline__ uint32_t pack_bf16(__nv_bfloat16 a, __nv_bfloat16 b) {
    __nv_bfloat162 t = __halves2bfloat162(a, b);
    return *(uint32_t*)&t;
}
__device__ __forceinline__ uint32_t pack_f2bf(float a, float b) {
    __nv_bfloat162 t = __floats2bfloat162_rn(a, b);
    return *(uint32_t*)&t;
}

// ---------------------------------------------------------------------------
// prep kernels
// ---------------------------------------------------------------------------
__global__ __launch_bounds__(256) void prep_x(const float* __restrict__ x, int n4)
{
    int i = blockIdx.x * 256 + threadIdx.x;
    if (i >= n4) return;
    float4 v = ((const float4*)x)[i];
    v.x = to_tf32(v.x); v.y = to_tf32(v.y);
    v.z = to_tf32(v.z); v.w = to_tf32(v.w);
    ((float4*)g_xt)[i] = v;
}

__global__ __launch_bounds__(256) void prep_er(const float* __restrict__ er)
{
    int i = blockIdx.x * 256 + threadIdx.x;
    if (i >= T_LEN * DH / 4) return;
    float4 v = ((const float4*)er)[i];
    float f[4] = {v.x, v.y, v.z, v.w};
    __nv_bfloat16 h[4], l[4];
    #pragma unroll
    for (int j = 0; j < 4; j++) {
        h[j] = __float2bfloat16(f[j]);
        l[j] = __float2bfloat16(f[j] - __bfloat162float(h[j]));
    }
    __nv_bfloat162* oh = (__nv_bfloat162*)g_erh;
    __nv_bfloat162* ol = (__nv_bfloat162*)g_erl;
    oh[2 * i]     = __halves2bfloat162(h[0], h[1]);
    oh[2 * i + 1] = __halves2bfloat162(h[2], h[3]);
    ol[2 * i]     = __halves2bfloat162(l[0], l[1]);
    ol[2 * i + 1] = __halves2bfloat162(l[2], l[3]);
}

__global__ __launch_bounds__(256) void prep_w(const float* __restrict__ Wq,
                                              const float* __restrict__ Wk,
                                              const float* __restrict__ Wv)
{
    const float* W = (blockIdx.z == 0) ? Wq : (blockIdx.z == 1) ? Wk : Wv;
    __shared__ float t[32][33];
    int tx = threadIdx.x, ty = threadIdx.y;        // 32 x 8
    int n0 = blockIdx.x * 32, k0 = blockIdx.y * 32;
    #pragma unroll
    for (int i = 0; i < 4; i++)
        t[ty + 8 * i][tx] = W[(size_t)(k0 + ty + 8 * i) * DM + n0 + tx];
    __syncthreads();
    float* o = g_wt + (size_t)blockIdx.z * DM * DM;
    #pragma unroll
    for (int i = 0; i < 4; i++) {
        int n = n0 + ty + 8 * i;
        o[(size_t)n * DM + k0 + tx] = to_tf32(t[tx][ty + 8 * i]);
    }
}

// ---------------------------------------------------------------------------
// proj_mma: tf32 single-pass (2 mma per K=16 vs bf16 3-pass's 3).
// Persistent grid, 128x128 tiles, cp.async 2-stage, ldmatrix on fp32 data
// (an 8x8 b16 matrix = 8 rows x 4 fp32: lane l -> fp32[l>>2][l&3], which is
// exactly the tf32 m16n8k8 fragment pattern). Epilogue still emits bf16
// hi/lo q/k/v for rel/attn (those kernels unchanged).
// ---------------------------------------------------------------------------
#define KC 32
#define NCHUNK (DM / KC)            // 32
#define SPADF 36                    // smem row stride in fp32 (144 B)
#define FROW 144
#define ARRF_B (128 * FROW)         // 18432 bytes per array
#define STAGEF_B (2 * ARRF_B)       // 36864 (A, B)
#define PROJ_SMEM (2 * STAGEF_B)    // 73728
#define PROJ_GRID 592               // 2 CTAs x 296 slots

__global__ __launch_bounds__(256, 2) void proj_mma(const float* __restrict__ bq,
                                                   const float* __restrict__ bk,
                                                   const float* __restrict__ bv,
                                                   int mTiles)
{
    extern __shared__ char sm[];
    uint32_t smb = smem_u32(sm);

    int tid = threadIdx.x;
    int wid = tid >> 5, lane = tid & 31;
    int g = lane >> 2, tig = lane & 3;
    int l15 = lane & 15;
    int wm = wid >> 2, wn = wid & 3;             // 2 x 4 warp grid

    // cp.async mapping: per array 128 rows x 128 B; idx = tid + 256j (j<4)
    // row = idx>>3, 16B-col = idx&7
    // ldmatrix offsets (fp32 data, 144 B rows)
    uint32_t aOff = (uint32_t)(((wm * 64) + (lane & 7) + ((lane >> 3) & 1) * 8) * FROW
                               + (lane >> 4) * 16);
    uint32_t bOff = (uint32_t)(((wn * 32) + (l15 & 7)) * FROW + (l15 >> 3) * 16);

    int tilesPerMat = mTiles * 8;                 // 8 n-tiles per mat
    int total = 3 * tilesPerMat;

    #pragma unroll 1
    for (int tile = blockIdx.x; tile < total; tile += gridDim.x) {
        int mat = tile / tilesPerMat;
        int rem = tile - mat * tilesPerMat;
        int n0 = (rem & 7) << 7;
        int m0 = (rem >> 3) << 7;

        const float* bias = (mat == 0) ? bq : (mat == 1) ? bk : bv;
        __nv_bfloat16* outh = (mat == 0) ? g_qh : (mat == 1) ? g_kh : g_vh;
        __nv_bfloat16* outl = (mat == 0) ? g_ql : (mat == 1) ? g_kl : g_vl;
        const float* srcA = g_xt + (size_t)m0 * DM;
        const float* srcB = g_wt + (size_t)mat * DM * DM + (size_t)n0 * DM;

        float acc[4][4][4];
        #pragma unroll
        for (int i = 0; i < 4; i++)
            #pragma unroll
            for (int j = 0; j < 4; j++)
                #pragma unroll
                for (int r = 0; r < 4; r++) acc[i][j][r] = 0.f;

        auto issue = [&](int c) {
            uint32_t sb = smb + (uint32_t)(c & 1) * STAGEF_B;
            int k0 = c * KC;
            #pragma unroll
            for (int j = 0; j < 4; j++) {
                int idx = tid + j * 256;
                int row = idx >> 3, c16 = idx & 7;
                uint32_t dof = (uint32_t)(row * FROW + c16 * 16);
                CP16(sb + dof, srcA + (size_t)row * DM + k0 + c16 * 4);
                CP16(sb + ARRF_B + dof, srcB + (size_t)row * DM + k0 + c16 * 4);
            }
            CP_COMMIT();
        };

        issue(0);

        #pragma unroll 1
        for (int c = 0; c < NCHUNK; c++) {
            if (c + 1 < NCHUNK) { issue(c + 1); CP_WAIT(1); }
            else                { CP_WAIT(0); }
            __syncthreads();

            uint32_t sb = smb + (uint32_t)(c & 1) * STAGEF_B;
            uint32_t aB = sb + aOff;
            uint32_t bB = sb + ARRF_B + bOff;

            #pragma unroll
            for (int ks = 0; ks < 4; ks++) {        // 4 k8 steps per K=32 chunk
                uint32_t kb = (uint32_t)ks * 32;    // 8 fp32 = 32 B per step
                uint32_t vb[4][2];
                #pragma unroll
                for (int nf = 0; nf < 4; nf++)
                    LDMX2(vb[nf][0], vb[nf][1], bB + (uint32_t)nf * 8 * FROW + kb);
                #pragma unroll
                for (int mf = 0; mf < 4; mf++) {
                    uint32_t a0, a1, a2, a3;
                    LDMX4(a0, a1, a2, a3, aB + (uint32_t)mf * 16 * FROW + kb);
                    #pragma unroll
                    for (int nf = 0; nf < 4; nf++)
                        MMATF32(acc[mf][nf], a0, a1, a2, a3, vb[nf][0], vb[nf][1]);
                }
            }
            __syncthreads();
        }

        // Epilogue: bias + split to bf16 hi/lo + scatter to [b,h,t,d]
        #pragma unroll
        for (int mf = 0; mf < 4; mf++) {
            #pragma unroll
            for (int nf = 0; nf < 4; nf++) {
                int n = n0 + wn * 32 + nf * 8 + tig * 2;
                int h = n >> 6, d = n & 63;
                float b0 = bias[n], b1 = bias[n + 1];
                #pragma unroll
                for (int half = 0; half < 2; half++) {
                    int m = m0 + wm * 64 + mf * 16 + g + half * 8;
                    int b = m >> 10, t = m & 1023;
                    size_t idx = (((size_t)b * HEADS + h) * T_LEN + t) * DH + d;
                    float v0 = acc[mf][nf][half * 2] + b0;
                    float v1 = acc[mf][nf][half * 2 + 1] + b1;
                    __nv_bfloat16 h0 = __float2bfloat16(v0);
                    __nv_bfloat16 h1 = __float2bfloat16(v1);
                    *(uint32_t*)&outh[idx] = pack_bf16(h0, h1);
                    *(uint32_t*)&outl[idx] = pack_f2bf(v0 - __bfloat162float(h0),
                                                       v1 - __bfloat162float(h1));
                }
            }
        }
        __syncthreads();   // epilogue done before next tile reuses smem
    }
}

// ---------------------------------------------------------------------------
// rel_mma: banded R[bh][t][c] = q[bh][t].Er[c] on HMMA (3-pass hi/lo).
// ---------------------------------------------------------------------------
#define EPAD 72
#define EROW (EPAD * 2)   // 144 bytes

__global__ __launch_bounds__(128) void rel_mma()
{
    __shared__ __nv_bfloat16 sEh[64][EPAD];
    __shared__ __nv_bfloat16 sEl[64][EPAD];

    int sb = blockIdx.x, tb = blockIdx.y, bh = blockIdx.z;
    if (tb + sb < 15) return;   // tile never read under causal mask

    int tid = threadIdx.x, w = tid >> 5, lane = tid & 31;
    int l15 = lane & 15;
    int t0 = tb * 64, s0 = sb * 64;

    const __nv_bfloat16* qh = g_qh + (size_t)bh * T_LEN * DH;
    const __nv_bfloat16* ql = g_ql + (size_t)bh * T_LEN * DH;

    for (int i = tid; i < 512; i += 128) {
        int r = i >> 3, c = (i & 7) * 8;
        *(uint4*)&sEh[r][c] = *(const uint4*)&g_erh[(s0 + r) * DH + c];
        *(uint4*)&sEl[r][c] = *(const uint4*)&g_erl[(s0 + r) * DH + c];
    }

    int rowA = t0 + w * 16 + (lane >> 2);
    int tig = lane & 3;
    uint32_t qfh[4][4], qfl[4][4];
    #pragma unroll
    for (int ks = 0; ks < 4; ks++) {
        int d0 = ks * 16 + tig * 2;
        qfh[ks][0] = *(const uint32_t*)&qh[(size_t)rowA * DH + d0];
        qfh[ks][1] = *(const uint32_t*)&qh[(size_t)(rowA + 8) * DH + d0];
        qfh[ks][2] = *(const uint32_t*)&qh[(size_t)rowA * DH + d0 + 8];
        qfh[ks][3] = *(const uint32_t*)&qh[(size_t)(rowA + 8) * DH + d0 + 8];
        qfl[ks][0] = *(const uint32_t*)&ql[(size_t)rowA * DH + d0];
        qfl[ks][1] = *(const uint32_t*)&ql[(size_t)(rowA + 8) * DH + d0];
        qfl[ks][2] = *(const uint32_t*)&ql[(size_t)rowA * DH + d0 + 8];
        qfl[ks][3] = *(const uint32_t*)&ql[(size_t)(rowA + 8) * DH + d0 + 8];
    }
    __syncthreads();

    float acc[8][4];
    #pragma unroll
    for (int f = 0; f < 8; f++)
        #pragma unroll
        for (int r = 0; r < 4; r++) acc[f][r] = 0.f;

    uint32_t eOff = (uint32_t)((l15 & 7) * EROW + (l15 >> 3) * 16);
    uint32_t eH = smem_u32(&sEh[0][0]) + eOff;
    uint32_t eL = smem_u32(&sEl[0][0]) + eOff;

    #pragma unroll
    for (int ks = 0; ks < 4; ks++) {
        uint32_t kb = (uint32_t)ks * 32;
        uint32_t ebh[8][2], ebl[8][2];
        #pragma unroll
        for (int nf = 0; nf < 8; nf++) {
            LDMX2(ebh[nf][0], ebh[nf][1], eH + (uint32_t)nf * 8 * EROW + kb);
            LDMX2(ebl[nf][0], ebl[nf][1], eL + (uint32_t)nf * 8 * EROW + kb);
        }
        #pragma unroll
        for (int nf = 0; nf < 8; nf++)
            MMA16816(acc[nf], qfh[ks][0], qfh[ks][1], qfh[ks][2], qfh[ks][3],
                     ebh[nf][0], ebh[nf][1]);
        #pragma unroll
        for (int nf = 0; nf < 8; nf++)
            MMA16816(acc[nf], qfh[ks][0], qfh[ks][1], qfh[ks][2], qfh[ks][3],
                     ebl[nf][0], ebl[nf][1]);
        #pragma unroll
        for (int nf = 0; nf < 8; nf++)
            MMA16816(acc[nf], qfl[ks][0], qfl[ks][1], qfl[ks][2], qfl[ks][3],
                     ebh[nf][0], ebh[nf][1]);
    }

    float* Rg = g_R + (size_t)bh * T_LEN * T_LEN;
    #pragma unroll
    for (int nf = 0; nf < 8; nf++) {
        int c = s0 + nf * 8 + tig * 2;
        *(float2*)&Rg[(size_t)rowA * T_LEN + c] = make_float2(acc[nf][0], acc[nf][1]);
        *(float2*)&Rg[(size_t)(rowA + 8) * T_LEN + c] = make_float2(acc[nf][2], acc[nf][3]);
    }
}

// ---------------------------------------------------------------------------
// attn_mma: FA2 flash attention on HMMA (3-pass hi/lo).
// 128-row t-tile, 256 threads. cp.async double-buffered K/V tiles.
// ---------------------------------------------------------------------------
#define ARR_AT (64 * EROW)          // 9216 B per array (64 rows x 144 B)
#define STAGE_AT (4 * ARR_AT)       // 36864
#define AT_SMEM (2 * STAGE_AT)      // 73728

__global__ __launch_bounds__(256, 1) void attn_mma(float* __restrict__ out)
{
    extern __shared__ char smA[];
    uint32_t smb = smem_u32(smA);

    int tid = threadIdx.x, w = tid >> 5, lane = tid & 31;
    int g = lane >> 2, tig = lane & 3;
    int l15 = lane & 15;
    int tb = (int)gridDim.x - 1 - (int)blockIdx.x;   // heavy tiles first
    int bh = blockIdx.y;
    int t0 = tb * 128;

    const __nv_bfloat16* qh = g_qh + (size_t)bh * T_LEN * DH;
    const __nv_bfloat16* ql = g_ql + (size_t)bh * T_LEN * DH;
    const __nv_bfloat16* kh = g_kh + (size_t)bh * T_LEN * DH;
    const __nv_bfloat16* kl = g_kl + (size_t)bh * T_LEN * DH;
    const __nv_bfloat16* vh = g_vh + (size_t)bh * T_LEN * DH;
    const __nv_bfloat16* vl = g_vl + (size_t)bh * T_LEN * DH;
    const float* Rg = g_R + (size_t)bh * T_LEN * T_LEN;

    int rowA = t0 + w * 16 + g;
    int row1 = rowA + 8;

    uint32_t qfh[4][4], qfl[4][4];
    #pragma unroll
    for (int ks = 0; ks < 4; ks++) {
        int d0 = ks * 16 + tig * 2;
        qfh[ks][0] = *(const uint32_t*)&qh[(size_t)rowA * DH + d0];
        qfh[ks][1] = *(const uint32_t*)&qh[(size_t)row1 * DH + d0];
        qfh[ks][2] = *(const uint32_t*)&qh[(size_t)rowA * DH + d0 + 8];
        qfh[ks][3] = *(const uint32_t*)&qh[(size_t)row1 * DH + d0 + 8];
        qfl[ks][0] = *(const uint32_t*)&ql[(size_t)rowA * DH + d0];
        qfl[ks][1] = *(const uint32_t*)&ql[(size_t)row1 * DH + d0];
        qfl[ks][2] = *(const uint32_t*)&ql[(size_t)rowA * DH + d0 + 8];
        qfl[ks][3] = *(const uint32_t*)&ql[(size_t)row1 * DH + d0 + 8];
    }

    float m0 = -1e30f, m1 = -1e30f, l0 = 0.f, l1 = 0.f;
    float o[8][4];
    #pragma unroll
    for (int f = 0; f < 8; f++)
        #pragma unroll
        for (int r = 0; r < 4; r++) o[f][r] = 0.f;

    const float* R0 = Rg + (size_t)rowA * T_LEN + (T_LEN - 1 - rowA);
    const float* R1 = Rg + (size_t)row1 * T_LEN + (T_LEN - 1 - row1);

    int cr0 = tid >> 3;
    int cc0 = (tid & 7) * 8;
    uint32_t cOff0 = (uint32_t)(cr0 * EROW + cc0 * 2);
    uint32_t cOff1 = cOff0 + 32 * EROW;
    const __nv_bfloat16* kvsrc[4] = {kh, kl, vh, vl};

    auto issueKV = [&](int sbt) {
        uint32_t st = smb + (uint32_t)(sbt & 1) * STAGE_AT;
        int s0 = sbt * 64;
        #pragma unroll
        for (int a = 0; a < 4; a++) {
            const __nv_bfloat16* s = kvsrc[a] + (size_t)s0 * DH;
            uint32_t d = st + (uint32_t)a * ARR_AT;
            CP16(d + cOff0, s + (size_t)cr0 * DH + cc0);
            CP16(d + cOff1, s + (size_t)(cr0 + 32) * DH + cc0);
        }
        CP_COMMIT();
    };

    uint32_t kOff = (uint32_t)((l15 & 7) * EROW + (l15 >> 3) * 16);
    uint32_t vOff = (uint32_t)(((l15 & 7) + (l15 >> 3) * 8) * EROW);

    int sbMax = 2 * tb + 1;
    issueKV(0);

    #pragma unroll 1
    for (int sb = 0; sb <= sbMax; sb++) {
        int s0 = sb * 64;
        if (sb + 1 <= sbMax) { issueKV(sb + 1); CP_WAIT(1); }
        else                 { CP_WAIT(0); }
        __syncthreads();

        uint32_t st = smb + (uint32_t)(sb & 1) * STAGE_AT;
        uint32_t kBH = st + kOff;
        uint32_t kBL = st + ARR_AT + kOff;
        uint32_t vBH = st + 2 * ARR_AT + vOff;
        uint32_t vBL = st + 3 * ARR_AT + vOff;

        float s[8][4];
        #pragma unroll
        for (int f = 0; f < 8; f++)
            #pragma unroll
            for (int r = 0; r < 4; r++) s[f][r] = 0.f;

        #pragma unroll
        for (int ks = 0; ks < 4; ks++) {
            uint32_t kb = (uint32_t)ks * 32;
            uint32_t kbh[8][2], kbl[8][2];
            #pragma unroll
            for (int nf = 0; nf < 8; nf++) {
                LDMX2(kbh[nf][0], kbh[nf][1], kBH + (uint32_t)nf * 8 * EROW + kb);
                LDMX2(kbl[nf][0], kbl[nf][1], kBL + (uint32_t)nf * 8 * EROW + kb);
            }
            #pragma unroll
            for (int nf = 0; nf < 8; nf++)
                MMA16816(s[nf], qfh[ks][0], qfh[ks][1], qfh[ks][2], qfh[ks][3],
                         kbh[nf][0], kbh[nf][1]);
            #pragma unroll
            for (int nf = 0; nf < 8; nf++)
                MMA16816(s[nf], qfh[ks][0], qfh[ks][1], qfh[ks][2], qfh[ks][3],
                         kbl[nf][0], kbl[nf][1]);
            #pragma unroll
            for (int nf = 0; nf < 8; nf++)
                MMA16816(s[nf], qfl[ks][0], qfl[ks][1], qfl[ks][2], qfl[ks][3],
                         kbh[nf][0], kbh[nf][1]);
        }

        #pragma unroll
        for (int nf = 0; nf < 8; nf++) {
            int sc = s0 + nf * 8 + tig * 2;
            float r00 = R0[min(sc, rowA)];
            float r01 = R0[min(sc + 1, rowA)];
            float r10 = R1[min(sc, row1)];
            float r11 = R1[min(sc + 1, row1)];
            s[nf][0] = (sc     <= rowA) ? (s[nf][0] + r00) * 0.125f : -1e30f;
            s[nf][1] = (sc + 1 <= rowA) ? (s[nf][1] + r01) * 0.125f : -1e30f;
            s[nf][2] = (sc     <= row1) ? (s[nf][2] + r10) * 0.125f : -1e30f;
            s[nf][3] = (sc + 1 <= row1) ? (s[nf][3] + r11) * 0.125f : -1e30f;
        }

        float mx0 = -1e30f, mx1 = -1e30f;
        #pragma unroll
        for (int nf = 0; nf < 8; nf++) {
            mx0 = fmaxf(mx0, fmaxf(s[nf][0], s[nf][1]));
            mx1 = fmaxf(mx1, fmaxf(s[nf][2], s[nf][3]));
        }
        mx0 = fmaxf(mx0, __shfl_xor_sync(0xffffffffu, mx0, 1));
        mx0 = fmaxf(mx0, __shfl_xor_sync(0xffffffffu, mx0, 2));
        mx1 = fmaxf(mx1, __shfl_xor_sync(0xffffffffu, mx1, 1));
        mx1 = fmaxf(mx1, __shfl_xor_sync(0xffffffffu, mx1, 2));

        float mn0 = fmaxf(m0, mx0), a0 = __expf(m0 - mn0); m0 = mn0;
        float mn1 = fmaxf(m1, mx1), a1 = __expf(m1 - mn1); m1 = mn1;

        float rs0 = 0.f, rs1 = 0.f;
        #pragma unroll
        for (int nf = 0; nf < 8; nf++) {
            s[nf][0] = __expf(s[nf][0] - mn0);
            s[nf][1] = __expf(s[nf][1] - mn0);
            s[nf][2] = __expf(s[nf][2] - mn1);
            s[nf][3] = __expf(s[nf][3] - mn1);
            rs0 += s[nf][0] + s[nf][1];
            rs1 += s[nf][2] + s[nf][3];
        }
        rs0 += __shfl_xor_sync(0xffffffffu, rs0, 1);
        rs0 += __shfl_xor_sync(0xffffffffu, rs0, 2);
        rs1 += __shfl_xor_sync(0xffffffffu, rs1, 1);
        rs1 += __shfl_xor_sync(0xffffffffu, rs1, 2);
        l0 = l0 * a0 + rs0;
        l1 = l1 * a1 + rs1;
        #pragma unroll
        for (int f = 0; f < 8; f++) {
            o[f][0] *= a0; o[f][1] *= a0;
            o[f][2] *= a1; o[f][3] *= a1;
        }

        uint32_t ph[8][2], pl[8][2];
        #pragma unroll
        for (int f = 0; f < 8; f++) {
            __nv_bfloat16 h00 = __float2bfloat16(s[f][0]);
            __nv_bfloat16 h01 = __float2bfloat16(s[f][1]);
            __nv_bfloat16 h10 = __float2bfloat16(s[f][2]);
            __nv_bfloat16 h11 = __float2bfloat16(s[f][3]);
            ph[f][0] = pack_bf16(h00, h01);
            ph[f][1] = pack_bf16(h10, h11);
            pl[f][0] = pack_f2bf(s[f][0] - __bfloat162float(h00),
                                 s[f][1] - __bfloat162float(h01));
            pl[f][1] = pack_f2bf(s[f][2] - __bfloat162float(h10),
                                 s[f][3] - __bfloat162float(h11));
        }

        #pragma unroll
        for (int j = 0; j < 4; j++) {
            uint32_t aH0 = ph[2 * j][0], aH1 = ph[2 * j][1];
            uint32_t aH2 = ph[2 * j + 1][0], aH3 = ph[2 * j + 1][1];
            uint32_t aL0 = pl[2 * j][0], aL1 = pl[2 * j][1];
            uint32_t aL2 = pl[2 * j + 1][0], aL3 = pl[2 * j + 1][1];
            uint32_t jrow = (uint32_t)(j * 16) * EROW;
            uint32_t vbh[8][2], vbl[8][2];
            #pragma unroll
            for (int nf = 0; nf < 8; nf++) {
                LDMX2T(vbh[nf][0], vbh[nf][1], vBH + jrow + (uint32_t)nf * 16);
                LDMX2T(vbl[nf][0], vbl[nf][1], vBL + jrow + (uint32_t)nf * 16);
            }
            #pragma unroll
            for (int nf = 0; nf < 8; nf++)
                MMA16816(o[nf], aH0, aH1, aH2, aH3, vbh[nf][0], vbh[nf][1]);
            #pragma unroll
            for (int nf = 0; nf < 8; nf++)
                MMA16816(o[nf], aH0, aH1, aH2, aH3, vbl[nf][0], vbl[nf][1]);
            #pragma unroll
            for (int nf = 0; nf < 8; nf++)
                MMA16816(o[nf], aL0, aL1, aL2, aL3, vbh[nf][0], vbh[nf][1]);
        }
        __syncthreads();
    }

    int b = bh >> 4, h = bh & 15;
    float i0 = 1.f / l0, i1 = 1.f / l1;
    #pragma unroll
    for (int nf = 0; nf < 8; nf++) {
        int d = nf * 8 + tig * 2;
        float* op0 = out + ((size_t)b * T_LEN + rowA) * DM + h * DH + d;
        float* op1 = out + ((size_t)b * T_LEN + row1) * DM + h * DH + d;
        *(float2*)op0 = make_float2(o[nf][0] * i0, o[nf][1] * i0);
        *(float2*)op1 = make_float2(o[nf][2] * i1, o[nf][3] * i1);
    }
}

// ---------------------------------------------------------------------------
extern "C" void kernel_launch(void* const* d_in, const int* in_sizes, int n_in,
                              void* d_out, int out_size)
{
    const float* x  = (const float*)d_in[0];
    const float* Wq = (const float*)d_in[1];
    const float* bq = (const float*)d_in[2];
    const float* Wk = (const float*)d_in[3];
    const float* bk = (const float*)d_in[4];
    const float* Wv = (const float*)d_in[5];
    const float* bv = (const float*)d_in[6];
    const float* Er = (const float*)d_in[7];
    float* out = (float*)d_out;

    int NB = in_sizes[0] / (T_LEN * DM);
    if (NB > NB_MAX) NB = NB_MAX;

    cudaFuncSetAttribute(proj_mma, cudaFuncAttributeMaxDynamicSharedMemorySize,
                         PROJ_SMEM);
    cudaFuncSetAttribute(attn_mma, cudaFuncAttributeMaxDynamicSharedMemorySize,
                         AT_SMEM);

    // 0) tf32-truncate x, transpose+truncate W; Er -> bf16 hi/lo
    int n4 = NB * T_LEN * DM / 4;
    prep_x<<<(n4 + 255) / 256, 256>>>(x, n4);
    prep_er<<<(T_LEN * DH / 4 + 255) / 256, 256>>>(Er);
    prep_w<<<dim3(32, 32, 3), dim3(32, 8)>>>(Wq, Wk, Wv);

    // 1) q,k,v projections: tf32 single-pass (2 mma / K16 instead of 3)
    int mTiles = NB * 8;
    int totalTiles = 3 * mTiles * 8;
    int pgrid = totalTiles < PROJ_GRID ? totalTiles : PROJ_GRID;
    proj_mma<<<pgrid, 256, PROJ_SMEM>>>(bq, bk, bv, mTiles);

    // 2) relative scores R = q @ Er^T (banded) on HMMA
    dim3 rgrid(16, 16, NB * HEADS);
    rel_mma<<<rgrid, 128>>>();

    // 3) flash attention on HMMA (128-row t-tiles, heavy-first order)
    dim3 agrid(8, NB * HEADS);
    attn_mma<<<agrid, 256, AT_SMEM>>>(out);
}

// round 16
// speedup vs baseline: 1.1889x; 1.0268x over previous
#include <cuda_runtime.h>
#include <cuda_bf16.h>
#include <cstdint>

// Problem constants (fixed by the reference: N=4, T=1024, H=16, D_HEAD=64)
#define T_LEN 1024
#define HEADS 16
#define DH 64
#define NB_MAX 4
#define DM 1024

// ---------------------------------------------------------------------------
// Scratch (device globals — no allocation allowed in kernel_launch)
// ---------------------------------------------------------------------------
__device__ __align__(16) float g_R[(size_t)NB_MAX * HEADS * T_LEN * T_LEN]; // [bh][t][c], c=s-t+1023
__device__ __align__(16) float g_xt[NB_MAX * T_LEN * DM];   // x, tf32-truncated
__device__ __align__(16) float g_wt[3 * DM * DM];           // W^T [mat][n][k], tf32
__device__ __align__(16) float g_qt[NB_MAX * HEADS * T_LEN * DH];  // q, tf32
__device__ __align__(16) float g_kt[NB_MAX * HEADS * T_LEN * DH];  // k, tf32
__device__ __align__(16) __nv_bfloat16 g_vh[NB_MAX * HEADS * T_LEN * DH];
__device__ __align__(16) __nv_bfloat16 g_vl[NB_MAX * HEADS * T_LEN * DH];
__device__ __align__(16) float g_ert[T_LEN * DH];           // Er, tf32

// mma.sync m16n8k16 row.col f32.bf16.bf16.f32 (base PTX — works on sm_100)
#define MMA16816(d, a0, a1, a2, a3, b0, b1)                                   \
    asm volatile(                                                             \
        "mma.sync.aligned.m16n8k16.row.col.f32.bf16.bf16.f32 "                \
        "{%0,%1,%2,%3}, {%4,%5,%6,%7}, {%8,%9}, {%0,%1,%2,%3};"               \
        : "+f"((d)[0]), "+f"((d)[1]), "+f"((d)[2]), "+f"((d)[3])              \
        : "r"(a0), "r"(a1), "r"(a2), "r"(a3), "r"(b0), "r"(b1))

// mma.sync m16n8k8 tf32 (base PTX sm_80+)
#define MMATF32(d, a0, a1, a2, a3, b0, b1)                                    \
    asm volatile(                                                             \
        "mma.sync.aligned.m16n8k8.row.col.f32.tf32.tf32.f32 "                 \
        "{%0,%1,%2,%3}, {%4,%5,%6,%7}, {%8,%9}, {%0,%1,%2,%3};"               \
        : "+f"((d)[0]), "+f"((d)[1]), "+f"((d)[2]), "+f"((d)[3])              \
        : "r"(a0), "r"(a1), "r"(a2), "r"(a3), "r"(b0), "r"(b1))

#define LDMX4(r0, r1, r2, r3, a)                                              \
    asm volatile("ldmatrix.sync.aligned.m8n8.x4.shared.b16 {%0,%1,%2,%3}, [%4];" \
                 : "=r"(r0), "=r"(r1), "=r"(r2), "=r"(r3) : "r"(a))
#define LDMX2(r0, r1, a)                                                      \
    asm volatile("ldmatrix.sync.aligned.m8n8.x2.shared.b16 {%0,%1}, [%2];"    \
                 : "=r"(r0), "=r"(r1) : "r"(a))
#define LDMX2T(r0, r1, a)                                                     \
    asm volatile("ldmatrix.sync.aligned.m8n8.x2.trans.shared.b16 {%0,%1}, [%2];" \
                 : "=r"(r0), "=r"(r1) : "r"(a))
#define CP16(dst_u32, src)                                                    \
    asm volatile("cp.async.cg.shared.global [%0], [%1], 16;"                  \
                 :: "r"(dst_u32), "l"(src))
#define CP_COMMIT() asm volatile("cp.async.commit_group;" ::: "memory")
#define CP_WAIT(n)  asm volatile("cp.async.wait_group %0;" :: "n"(n) : "memory")

__device__ __forceinline__ uint32_t smem_u32(const void* p) {
    uint32_t a;
    asm("{ .reg .u64 t; cvta.to.shared.u64 t, %1; cvt.u32.u64 %0, t; }"
        : "=r"(a) : "l"(p));
    return a;
}
__device__ __forceinline__ float to_tf32(float x) {
    uint32_t b;
    asm("cvt.rna.tf32.f32 %0, %1;" : "=r"(b) : "f"(x));
    return __uint_as_float(b);
}
__device__ __forceinline__ uint32_t pack_bf16(__nv_bfloat16 a, __nv_bfloat16 b) {
    __nv_bfloat162 t = __halves2bfloat162(a, b);
    return *(uint32_t*)&t;
}
__device__ __forceinline__ uint32_t pack_f2bf(float a, float b) {
    __nv_bfloat162 t = __floats2bfloat162_rn(a, b);
    return *(uint32_t*)&t;
}

// ---------------------------------------------------------------------------
// prep kernels
// ---------------------------------------------------------------------------
__global__ __launch_bounds__(256) void prep_x(const float* __restrict__ x, int n4)
{
    int i = blockIdx.x * 256 + threadIdx.x;
    if (i >= n4) return;
    float4 v = ((const float4*)x)[i];
    v.x = to_tf32(v.x); v.y = to_tf32(v.y);
    v.z = to_tf32(v.z); v.w = to_tf32(v.w);
    ((float4*)g_xt)[i] = v;
}

__global__ __launch_bounds__(256) void prep_er(const float* __restrict__ er)
{
    int i = blockIdx.x * 256 + threadIdx.x;
    if (i >= T_LEN * DH / 4) return;
    float4 v = ((const float4*)er)[i];
    v.x = to_tf32(v.x); v.y = to_tf32(v.y);
    v.z = to_tf32(v.z); v.w = to_tf32(v.w);
    ((float4*)g_ert)[i] = v;
}

__global__ __launch_bounds__(256) void prep_w(const float* __restrict__ Wq,
                                              const float* __restrict__ Wk,
                                              const float* __restrict__ Wv)
{
    const float* W = (blockIdx.z == 0) ? Wq : (blockIdx.z == 1) ? Wk : Wv;
    __shared__ float t[32][33];
    int tx = threadIdx.x, ty = threadIdx.y;        // 32 x 8
    int n0 = blockIdx.x * 32, k0 = blockIdx.y * 32;
    #pragma unroll
    for (int i = 0; i < 4; i++)
        t[ty + 8 * i][tx] = W[(size_t)(k0 + ty + 8 * i) * DM + n0 + tx];
    __syncthreads();
    float* o = g_wt + (size_t)blockIdx.z * DM * DM;
    #pragma unroll
    for (int i = 0; i < 4; i++) {
        int n = n0 + ty + 8 * i;
        o[(size_t)n * DM + k0 + tx] = to_tf32(t[tx][ty + 8 * i]);
    }
}

// ---------------------------------------------------------------------------
// proj_mma: tf32 single-pass. Persistent grid, 128x128 tiles, cp.async
// 2-stage, ldmatrix on fp32 data. q,k emitted as tf32 fp32; v as bf16 hi/lo.
// ---------------------------------------------------------------------------
#define KC 32
#define NCHUNK (DM / KC)            // 32
#define FROW 144
#define ARRF_B (128 * FROW)         // 18432 bytes per array
#define STAGEF_B (2 * ARRF_B)       // 36864 (A, B)
#define PROJ_SMEM (2 * STAGEF_B)    // 73728
#define PROJ_GRID 592               // 2 CTAs x 296 slots

__global__ __launch_bounds__(256, 2) void proj_mma(const float* __restrict__ bq,
                                                   const float* __restrict__ bk,
                                                   const float* __restrict__ bv,
                                                   int mTiles)
{
    extern __shared__ char sm[];
    uint32_t smb = smem_u32(sm);

    int tid = threadIdx.x;
    int wid = tid >> 5, lane = tid & 31;
    int g = lane >> 2, tig = lane & 3;
    int l15 = lane & 15;
    int wm = wid >> 2, wn = wid & 3;             // 2 x 4 warp grid

    uint32_t aOff = (uint32_t)(((wm * 64) + (lane & 7) + ((lane >> 3) & 1) * 8) * FROW
                               + (lane >> 4) * 16);
    uint32_t bOff = (uint32_t)(((wn * 32) + (l15 & 7)) * FROW + (l15 >> 3) * 16);

    int tilesPerMat = mTiles * 8;                 // 8 n-tiles per mat
    int total = 3 * tilesPerMat;

    #pragma unroll 1
    for (int tile = blockIdx.x; tile < total; tile += gridDim.x) {
        int mat = tile / tilesPerMat;
        int rem = tile - mat * tilesPerMat;
        int n0 = (rem & 7) << 7;
        int m0 = (rem >> 3) << 7;

        const float* bias = (mat == 0) ? bq : (mat == 1) ? bk : bv;
        const float* srcA = g_xt + (size_t)m0 * DM;
        const float* srcB = g_wt + (size_t)mat * DM * DM + (size_t)n0 * DM;

        float acc[4][4][4];
        #pragma unroll
        for (int i = 0; i < 4; i++)
            #pragma unroll
            for (int j = 0; j < 4; j++)
                #pragma unroll
                for (int r = 0; r < 4; r++) acc[i][j][r] = 0.f;

        auto issue = [&](int c) {
            uint32_t sb = smb + (uint32_t)(c & 1) * STAGEF_B;
            int k0 = c * KC;
            #pragma unroll
            for (int j = 0; j < 4; j++) {
                int idx = tid + j * 256;
                int row = idx >> 3, c16 = idx & 7;
                uint32_t dof = (uint32_t)(row * FROW + c16 * 16);
                CP16(sb + dof, srcA + (size_t)row * DM + k0 + c16 * 4);
                CP16(sb + ARRF_B + dof, srcB + (size_t)row * DM + k0 + c16 * 4);
            }
            CP_COMMIT();
        };

        issue(0);

        #pragma unroll 1
        for (int c = 0; c < NCHUNK; c++) {
            if (c + 1 < NCHUNK) { issue(c + 1); CP_WAIT(1); }
            else                { CP_WAIT(0); }
            __syncthreads();

            uint32_t sb = smb + (uint32_t)(c & 1) * STAGEF_B;
            uint32_t aB = sb + aOff;
            uint32_t bB = sb + ARRF_B + bOff;

            #pragma unroll
            for (int ks = 0; ks < 4; ks++) {        // 4 k8 steps per K=32 chunk
                uint32_t kb = (uint32_t)ks * 32;    // 8 fp32 = 32 B per step
                uint32_t vb[4][2];
                #pragma unroll
                for (int nf = 0; nf < 4; nf++)
                    LDMX2(vb[nf][0], vb[nf][1], bB + (uint32_t)nf * 8 * FROW + kb);
                #pragma unroll
                for (int mf = 0; mf < 4; mf++) {
                    uint32_t a0, a1, a2, a3;
                    LDMX4(a0, a1, a2, a3, aB + (uint32_t)mf * 16 * FROW + kb);
                    #pragma unroll
                    for (int nf = 0; nf < 4; nf++)
                        MMATF32(acc[mf][nf], a0, a1, a2, a3, vb[nf][0], vb[nf][1]);
                }
            }
            __syncthreads();
        }

        // Epilogue: bias + scatter to [b,h,t,d].
        //   mat 0/1 (q,k): tf32-rounded fp32 (feeds tf32 QK / rel)
        //   mat 2   (v)  : bf16 hi/lo (feeds bf16 3-pass PV)
        #pragma unroll
        for (int mf = 0; mf < 4; mf++) {
            #pragma unroll
            for (int nf = 0; nf < 4; nf++) {
                int n = n0 + wn * 32 + nf * 8 + tig * 2;
                int h = n >> 6, d = n & 63;
                float b0 = bias[n], b1 = bias[n + 1];
                #pragma unroll
                for (int half = 0; half < 2; half++) {
                    int m = m0 + wm * 64 + mf * 16 + g + half * 8;
                    int b = m >> 10, t = m & 1023;
                    size_t idx = (((size_t)b * HEADS + h) * T_LEN + t) * DH + d;
                    float v0 = acc[mf][nf][half * 2] + b0;
                    float v1 = acc[mf][nf][half * 2 + 1] + b1;
                    if (mat < 2) {
                        float* outf = (mat == 0) ? g_qt : g_kt;
                        *(float2*)&outf[idx] = make_float2(to_tf32(v0), to_tf32(v1));
                    } else {
                        __nv_bfloat16 h0 = __float2bfloat16(v0);
                        __nv_bfloat16 h1 = __float2bfloat16(v1);
                        *(uint32_t*)&g_vh[idx] = pack_bf16(h0, h1);
                        *(uint32_t*)&g_vl[idx] = pack_f2bf(v0 - __bfloat162float(h0),
                                                           v1 - __bfloat162float(h1));
                    }
                }
            }
        }
        __syncthreads();   // epilogue done before next tile reuses smem
    }
}

// ---------------------------------------------------------------------------
// rel_mma: banded R[bh][t][c] = q[bh][t].Er[c] on tf32 single-pass.
// q A-frags direct from g_qt; Er B-frags via ldmatrix on fp32 smem.
// ---------------------------------------------------------------------------
#define EROWF 272   // 68 fp32 per row (64 data + pad), 16B multiple

__global__ __launch_bounds__(128) void rel_mma()
{
    __shared__ __align__(16) float sEr[64][68];

    int sb = blockIdx.x, tb = blockIdx.y, bh = blockIdx.z;
    if (tb + sb < 15) return;   // tile never read under causal mask

    int tid = threadIdx.x, w = tid >> 5, lane = tid & 31;
    int l15 = lane & 15;
    int t0 = tb * 64, s0 = sb * 64;

    const float* qt = g_qt + (size_t)bh * T_LEN * DH;

    for (int i = tid; i < 1024; i += 128) {
        int r = i >> 4, c4 = (i & 15) * 4;
        *(uint4*)&sEr[r][c4] = *(const uint4*)&g_ert[(s0 + r) * DH + c4];
    }

    int rowA = t0 + w * 16 + (lane >> 2);
    int tig = lane & 3;
    // q A-fragments: 8 k8 steps over d
    uint32_t qf[8][4];
    #pragma unroll
    for (int ks = 0; ks < 8; ks++) {
        int d0 = ks * 8 + tig;
        qf[ks][0] = __float_as_uint(qt[(size_t)rowA * DH + d0]);
        qf[ks][1] = __float_as_uint(qt[(size_t)(rowA + 8) * DH + d0]);
        qf[ks][2] = __float_as_uint(qt[(size_t)rowA * DH + d0 + 4]);
        qf[ks][3] = __float_as_uint(qt[(size_t)(rowA + 8) * DH + d0 + 4]);
    }
    __syncthreads();

    float acc[8][4];
    #pragma unroll
    for (int f = 0; f < 8; f++)
        #pragma unroll
        for (int r = 0; r < 4; r++) acc[f][r] = 0.f;

    uint32_t eOff = (uint32_t)((l15 & 7) * EROWF + (l15 >> 3) * 16);
    uint32_t eB = smem_u32(&sEr[0][0]) + eOff;

    #pragma unroll
    for (int ks = 0; ks < 8; ks++) {
        uint32_t kb = (uint32_t)ks * 32;
        uint32_t eb[8][2];
        #pragma unroll
        for (int nf = 0; nf < 8; nf++)
            LDMX2(eb[nf][0], eb[nf][1], eB + (uint32_t)nf * 8 * EROWF + kb);
        #pragma unroll
        for (int nf = 0; nf < 8; nf++)
            MMATF32(acc[nf], qf[ks][0], qf[ks][1], qf[ks][2], qf[ks][3],
                    eb[nf][0], eb[nf][1]);
    }

    float* Rg = g_R + (size_t)bh * T_LEN * T_LEN;
    #pragma unroll
    for (int nf = 0; nf < 8; nf++) {
        int c = s0 + nf * 8 + tig * 2;
        *(float2*)&Rg[(size_t)rowA * T_LEN + c] = make_float2(acc[nf][0], acc[nf][1]);
        *(float2*)&Rg[(size_t)(rowA + 8) * T_LEN + c] = make_float2(acc[nf][2], acc[nf][3]);
    }
}

// ---------------------------------------------------------------------------
// attn_mma: FA2 flash attention. QK on tf32 single-pass (k fp32 in smem),
// PV on bf16 3-pass. 128-row t-tile, 256 threads, cp.async double-buffered.
// ---------------------------------------------------------------------------
#define EROW 144                     // bf16 V rows: 72 bf16
#define ARR_K (64 * EROWF)           // 17408 B (64 rows x 272 B fp32)
#define ARR_V (64 * EROW)            // 9216 B
#define STAGE_AT (ARR_K + 2 * ARR_V) // 35840
#define AT_SMEM (2 * STAGE_AT)       // 71680

__global__ __launch_bounds__(256, 1) void attn_mma(float* __restrict__ out)
{
    extern __shared__ char smA[];
    uint32_t smb = smem_u32(smA);

    int tid = threadIdx.x, w = tid >> 5, lane = tid & 31;
    int g = lane >> 2, tig = lane & 3;
    int l15 = lane & 15;
    int tb = (int)gridDim.x - 1 - (int)blockIdx.x;   // heavy tiles first
    int bh = blockIdx.y;
    int t0 = tb * 128;

    const float* qt = g_qt + (size_t)bh * T_LEN * DH;
    const float* kt = g_kt + (size_t)bh * T_LEN * DH;
    const __nv_bfloat16* vh = g_vh + (size_t)bh * T_LEN * DH;
    const __nv_bfloat16* vl = g_vl + (size_t)bh * T_LEN * DH;
    const float* Rg = g_R + (size_t)bh * T_LEN * T_LEN;

    int rowA = t0 + w * 16 + g;
    int row1 = rowA + 8;

    // q A-fragments (tf32): 8 k8 steps over d, held for whole kernel
    uint32_t qf[8][4];
    #pragma unroll
    for (int ks = 0; ks < 8; ks++) {
        int d0 = ks * 8 + tig;
        qf[ks][0] = __float_as_uint(qt[(size_t)rowA * DH + d0]);
        qf[ks][1] = __float_as_uint(qt[(size_t)row1 * DH + d0]);
        qf[ks][2] = __float_as_uint(qt[(size_t)rowA * DH + d0 + 4]);
        qf[ks][3] = __float_as_uint(qt[(size_t)row1 * DH + d0 + 4]);
    }

    float m0 = -1e30f, m1 = -1e30f, l0 = 0.f, l1 = 0.f;
    float o[8][4];
    #pragma unroll
    for (int f = 0; f < 8; f++)
        #pragma unroll
        for (int r = 0; r < 4; r++) o[f][r] = 0.f;

    const float* R0 = Rg + (size_t)rowA * T_LEN + (T_LEN - 1 - rowA);
    const float* R1 = Rg + (size_t)row1 * T_LEN + (T_LEN - 1 - row1);

    auto issueKV = [&](int sbt) {
        uint32_t st = smb + (uint32_t)(sbt & 1) * STAGE_AT;
        int s0 = sbt * 64;
        // k: 64 rows x 256 B (16 chunks) -> 1024 chunks / 256 thr = 4 each
        #pragma unroll
        for (int j = 0; j < 4; j++) {
            int idx = tid + j * 256;
            int row = idx >> 4, c16 = idx & 15;
            CP16(st + (uint32_t)(row * EROWF + c16 * 16),
                 kt + (size_t)(s0 + row) * DH + c16 * 4);
        }
        // vh, vl: 64 rows x 128 B (8 chunks) -> 512 chunks -> 2 each
        #pragma unroll
        for (int j = 0; j < 2; j++) {
            int idx = tid + j * 256;
            int row = idx >> 3, c8 = idx & 7;
            uint32_t dof = (uint32_t)(row * EROW + c8 * 16);
            CP16(st + ARR_K + dof, vh + (size_t)(s0 + row) * DH + c8 * 8);
            CP16(st + ARR_K + ARR_V + dof, vl + (size_t)(s0 + row) * DH + c8 * 8);
        }
        CP_COMMIT();
    };

    uint32_t kOff = (uint32_t)((l15 & 7) * EROWF + (l15 >> 3) * 16);
    uint32_t vOff = (uint32_t)(((l15 & 7) + (l15 >> 3) * 8) * EROW);

    int sbMax = 2 * tb + 1;
    issueKV(0);

    #pragma unroll 1
    for (int sb = 0; sb <= sbMax; sb++) {
        int s0 = sb * 64;
        if (sb + 1 <= sbMax) { issueKV(sb + 1); CP_WAIT(1); }
        else                 { CP_WAIT(0); }
        __syncthreads();

        uint32_t st = smb + (uint32_t)(sb & 1) * STAGE_AT;
        uint32_t kB = st + kOff;
        uint32_t vBH = st + ARR_K + vOff;
        uint32_t vBL = st + ARR_K + ARR_V + vOff;

        // S = Q @ K^T (tf32 single-pass, 8 k8 steps)
        float s[8][4];
        #pragma unroll
        for (int f = 0; f < 8; f++)
            #pragma unroll
            for (int r = 0; r < 4; r++) s[f][r] = 0.f;

        #pragma unroll
        for (int ks = 0; ks < 8; ks++) {
            uint32_t kb = (uint32_t)ks * 32;
            uint32_t kbf[8][2];
            #pragma unroll
            for (int nf = 0; nf < 8; nf++)
                LDMX2(kbf[nf][0], kbf[nf][1], kB + (uint32_t)nf * 8 * EROWF + kb);
            #pragma unroll
            for (int nf = 0; nf < 8; nf++)
                MMATF32(s[nf], qf[ks][0], qf[ks][1], qf[ks][2], qf[ks][3],
                        kbf[nf][0], kbf[nf][1]);
        }

        // rel add + scale + causal mask (clamped indices keep loads in-bounds)
        #pragma unroll
        for (int nf = 0; nf < 8; nf++) {
            int sc = s0 + nf * 8 + tig * 2;
            float r00 = R0[min(sc, rowA)];
            float r01 = R0[min(sc + 1, rowA)];
            float r10 = R1[min(sc, row1)];
            float r11 = R1[min(sc + 1, row1)];
            s[nf][0] = (sc     <= rowA) ? (s[nf][0] + r00) * 0.125f : -1e30f;
            s[nf][1] = (sc + 1 <= rowA) ? (s[nf][1] + r01) * 0.125f : -1e30f;
            s[nf][2] = (sc     <= row1) ? (s[nf][2] + r10) * 0.125f : -1e30f;
            s[nf][3] = (sc + 1 <= row1) ? (s[nf][3] + r11) * 0.125f : -1e30f;
        }

        // online softmax
        float mx0 = -1e30f, mx1 = -1e30f;
        #pragma unroll
        for (int nf = 0; nf < 8; nf++) {
            mx0 = fmaxf(mx0, fmaxf(s[nf][0], s[nf][1]));
            mx1 = fmaxf(mx1, fmaxf(s[nf][2], s[nf][3]));
        }
        mx0 = fmaxf(mx0, __shfl_xor_sync(0xffffffffu, mx0, 1));
        mx0 = fmaxf(mx0, __shfl_xor_sync(0xffffffffu, mx0, 2));
        mx1 = fmaxf(mx1, __shfl_xor_sync(0xffffffffu, mx1, 1));
        mx1 = fmaxf(mx1, __shfl_xor_sync(0xffffffffu, mx1, 2));

        float mn0 = fmaxf(m0, mx0), a0 = __expf(m0 - mn0); m0 = mn0;
        float mn1 = fmaxf(m1, mx1), a1 = __expf(m1 - mn1); m1 = mn1;

        float rs0 = 0.f, rs1 = 0.f;
        #pragma unroll
        for (int nf = 0; nf < 8; nf++) {
            s[nf][0] = __expf(s[nf][0] - mn0);
            s[nf][1] = __expf(s[nf][1] - mn0);
            s[nf][2] = __expf(s[nf][2] - mn1);
            s[nf][3] = __expf(s[nf][3] - mn1);
            rs0 += s[nf][0] + s[nf][1];
            rs1 += s[nf][2] + s[nf][3];
        }
        rs0 += __shfl_xor_sync(0xffffffffu, rs0, 1);
        rs0 += __shfl_xor_sync(0xffffffffu, rs0, 2);
        rs1 += __shfl_xor_sync(0xffffffffu, rs1, 1);
        rs1 += __shfl_xor_sync(0xffffffffu, rs1, 2);
        l0 = l0 * a0 + rs0;
        l1 = l1 * a1 + rs1;
        #pragma unroll
        for (int f = 0; f < 8; f++) {
            o[f][0] *= a0; o[f][1] *= a0;
            o[f][2] *= a1; o[f][3] *= a1;
        }

        // P -> bf16 hi/lo A-fragments
        uint32_t ph[8][2], pl[8][2];
        #pragma unroll
        for (int f = 0; f < 8; f++) {
            __nv_bfloat16 h00 = __float2bfloat16(s[f][0]);
            __nv_bfloat16 h01 = __float2bfloat16(s[f][1]);
            __nv_bfloat16 h10 = __float2bfloat16(s[f][2]);
            __nv_bfloat16 h11 = __float2bfloat16(s[f][3]);
            ph[f][0] = pack_bf16(h00, h01);
            ph[f][1] = pack_bf16(h10, h11);
            pl[f][0] = pack_f2bf(s[f][0] - __bfloat162float(h00),
                                 s[f][1] - __bfloat162float(h01));
            pl[f][1] = pack_f2bf(s[f][2] - __bfloat162float(h10),
                                 s[f][3] - __bfloat162float(h11));
        }

        // O += P @ V (bf16 3-pass, pass-major); V B-frags via ldmatrix.trans
        #pragma unroll
        for (int j = 0; j < 4; j++) {
            uint32_t aH0 = ph[2 * j][0], aH1 = ph[2 * j][1];
            uint32_t aH2 = ph[2 * j + 1][0], aH3 = ph[2 * j + 1][1];
            uint32_t aL0 = pl[2 * j][0], aL1 = pl[2 * j][1];
            uint32_t aL2 = pl[2 * j + 1][0], aL3 = pl[2 * j + 1][1];
            uint32_t jrow = (uint32_t)(j * 16) * EROW;
            uint32_t vbh[8][2], vbl[8][2];
            #pragma unroll
            for (int nf = 0; nf < 8; nf++) {
                LDMX2T(vbh[nf][0], vbh[nf][1], vBH + jrow + (uint32_t)nf * 16);
                LDMX2T(vbl[nf][0], vbl[nf][1], vBL + jrow + (uint32_t)nf * 16);
            }
            #pragma unroll
            for (int nf = 0; nf < 8; nf++)
                MMA16816(o[nf], aH0, aH1, aH2, aH3, vbh[nf][0], vbh[nf][1]);
            #pragma unroll
            for (int nf = 0; nf < 8; nf++)
                MMA16816(o[nf], aH0, aH1, aH2, aH3, vbl[nf][0], vbl[nf][1]);
            #pragma unroll
            for (int nf = 0; nf < 8; nf++)
                MMA16816(o[nf], aL0, aL1, aL2, aL3, vbh[nf][0], vbh[nf][1]);
        }
        __syncthreads();   // all reads of this stage done before issueKV reuses it
    }

    // epilogue: out[b][t][h*64+d]
    int b = bh >> 4, h = bh & 15;
    float i0 = 1.f / l0, i1 = 1.f / l1;
    #pragma unroll
    for (int nf = 0; nf < 8; nf++) {
        int d = nf * 8 + tig * 2;
        float* op0 = out + ((size_t)b * T_LEN + rowA) * DM + h * DH + d;
        float* op1 = out + ((size_t)b * T_LEN + row1) * DM + h * DH + d;
        *(float2*)op0 = make_float2(o[nf][0] * i0, o[nf][1] * i0);
        *(float2*)op1 = make_float2(o[nf][2] * i1, o[nf][3] * i1);
    }
}

// ---------------------------------------------------------------------------
extern "C" void kernel_launch(void* const* d_in, const int* in_sizes, int n_in,
                              void* d_out, int out_size)
{
    const float* x  = (const float*)d_in[0];
    const float* Wq = (const float*)d_in[1];
    const float* bq = (const float*)d_in[2];
    const float* Wk = (const float*)d_in[3];
    const float* bk = (const float*)d_in[4];
    const float* Wv = (const float*)d_in[5];
    const float* bv = (const float*)d_in[6];
    const float* Er = (const float*)d_in[7];
    float* out = (float*)d_out;

    int NB = in_sizes[0] / (T_LEN * DM);
    if (NB > NB_MAX) NB = NB_MAX;

    cudaFuncSetAttribute(proj_mma, cudaFuncAttributeMaxDynamicSharedMemorySize,
                         PROJ_SMEM);
    cudaFuncSetAttribute(attn_mma, cudaFuncAttributeMaxDynamicSharedMemorySize,
                         AT_SMEM);

    // 0) tf32-truncate x, Er; transpose+truncate W
    int n4 = NB * T_LEN * DM / 4;
    prep_x<<<(n4 + 255) / 256, 256>>>(x, n4);
    prep_er<<<(T_LEN * DH / 4 + 255) / 256, 256>>>(Er);
    prep_w<<<dim3(32, 32, 3), dim3(32, 8)>>>(Wq, Wk, Wv);

    // 1) q,k,v projections: tf32 single-pass
    int mTiles = NB * 8;
    int totalTiles = 3 * mTiles * 8;
    int pgrid = totalTiles < PROJ_GRID ? totalTiles : PROJ_GRID;
    proj_mma<<<pgrid, 256, PROJ_SMEM>>>(bq, bk, bv, mTiles);

    // 2) relative scores R = q @ Er^T (banded) on tf32
    dim3 rgrid(16, 16, NB * HEADS);
    rel_mma<<<rgrid, 128>>>();

    // 3) flash attention: tf32 QK + bf16 3-pass PV
    dim3 agrid(8, NB * HEADS);
    attn_mma<<<agrid, 256, AT_SMEM>>>(out);
}